// round 11
// baseline (speedup 1.0000x reference)
#include <cuda_runtime.h>
#include <math_constants.h>

#define BN 4
#define TT 512
#define SS 512
#define IND 512
#define MD 256

// Scratch (allocation-free rule: __device__ globals)
__device__ float g_wqp[4][BN * TT * MD];        // wq split-K partials
__device__ float g_uhtp[2][BN * MD * SS];       // uht split-K partials [b][d][s]
__device__ float g_ctxp[2][BN * TT * MD];       // ctx split-K partials
__device__ float g_outp[3][BN * TT * IND];      // out split-K partials
__device__ float g_align_scratch[BN * TT * SS];

__device__ __forceinline__ float tanhap(float x) {
    float y;
    asm("tanh.approx.f32 %0, %1;" : "=f"(y) : "f"(x));
    return y;
}

// ---------------------------------------------------------------------------
// proj_kernel: 384 UNIFORM blocks of 128x64 tile x K=128 (1.05M MAC each).
//   z=0..3: g_wqp[z]   = inputs[:, z*128:(z+1)*128] @ Wq[:, z*128:..]^T
//   z=4,5:  g_uhtp[z-4]= mems[:, (z-4)*128:..] @ Wc[:, (z-4)*128:..]^T
//           (transposed store [b][d][s]; bias bc folded later in align)
// 256 threads, 8x4 per thread, TK=8, register prefetch.
// ---------------------------------------------------------------------------
__global__ __launch_bounds__(256) void proj_kernel(
    const float* __restrict__ inputs, const float* __restrict__ mems,
    const float* __restrict__ Wq, const float* __restrict__ Wc)
{
    const int z = blockIdx.z;
    const bool is_uht = (z >= 4);
    const int stride = is_uht ? MD : IND;
    const int koff = (is_uht ? (z - 4) : z) * 128;
    const float* A  = is_uht ? mems : inputs;
    const float* Bm = is_uht ? Wc : Wq;

    __shared__ float As[8][132];
    __shared__ float Bs[8][68];

    const int tid = threadIdx.x;
    const int bm = blockIdx.y * 128;
    const int bn = blockIdx.x * 64;
    const int lrA = tid >> 1;
    const int lcA = (tid & 1) * 4;
    const int tx = tid & 15, ty = tid >> 4;
    const int n0 = tx * 4, m0 = ty * 8;

    const float* Arow = A + (bm + lrA) * stride + koff + lcA;
    const float* Wrow = Bm + (bn + lrA) * stride + koff + lcA;

    float acc[8][4];
#pragma unroll
    for (int i = 0; i < 8; i++)
#pragma unroll
        for (int j = 0; j < 4; j++) acc[i][j] = 0.f;

    float4 a4 = *(const float4*)Arow;
    float4 b4 = make_float4(0.f, 0.f, 0.f, 0.f);
    if (tid < 128) b4 = *(const float4*)Wrow;

    for (int k0 = 0; k0 < 128; k0 += 8) {
        As[lcA + 0][lrA] = a4.x; As[lcA + 1][lrA] = a4.y;
        As[lcA + 2][lrA] = a4.z; As[lcA + 3][lrA] = a4.w;
        if (tid < 128) {
            Bs[lcA + 0][lrA] = b4.x; Bs[lcA + 1][lrA] = b4.y;
            Bs[lcA + 2][lrA] = b4.z; Bs[lcA + 3][lrA] = b4.w;
        }
        __syncthreads();
        const int kn = k0 + 8;
        if (kn < 128) {
            a4 = *(const float4*)(Arow + kn);
            if (tid < 128) b4 = *(const float4*)(Wrow + kn);
        }
#pragma unroll
        for (int kk = 0; kk < 8; kk++) {
            float4 x0 = *(const float4*)&As[kk][m0];
            float4 x1 = *(const float4*)&As[kk][m0 + 4];
            float4 y  = *(const float4*)&Bs[kk][n0];
            float am[8] = {x0.x, x0.y, x0.z, x0.w, x1.x, x1.y, x1.z, x1.w};
            float bb[4] = {y.x, y.y, y.z, y.w};
#pragma unroll
            for (int i = 0; i < 8; i++)
#pragma unroll
                for (int j = 0; j < 4; j++) acc[i][j] += am[i] * bb[j];
        }
        __syncthreads();
    }

    if (!is_uht) {
        float* dst = g_wqp[z];
#pragma unroll
        for (int i = 0; i < 8; i++) {
            float4 r = make_float4(acc[i][0], acc[i][1], acc[i][2], acc[i][3]);
            *(float4*)&dst[(bm + m0 + i) * MD + bn + n0] = r;
        }
    } else {
        float* dst = g_uhtp[z - 4];
#pragma unroll
        for (int i = 0; i < 8; i++) {
            const int m = bm + m0 + i;
            const int b = m >> 9;
            const int s = m & 511;
#pragma unroll
            for (int j = 0; j < 4; j++)
                dst[b * (MD * SS) + (bn + n0 + j) * SS + s] = acc[i][j];
        }
    }
}

// ---------------------------------------------------------------------------
// align_kernel: 8-t x 64-s work items (smem ~75KB -> 3 blocks/SM).
// Grid (8 s-chunks, 64 t-tiles, b). Early-exit on masked chunks.
// Folds wq = sum of 4 partials, uh = sum of 2 partials + bc.
// Warp = 1 t-row x 64 s (2 s per lane). Writes RAW scores to pa.
// ---------------------------------------------------------------------------
__global__ __launch_bounds__(256) void align_kernel(
    const int* __restrict__ mem_masks, const float* __restrict__ v,
    const float* __restrict__ bc, float* __restrict__ pa)
{
    const int b = blockIdx.z;
    const int t0 = blockIdx.y * 8;
    const int c = blockIdx.x;
    const int len = mem_masks[b];
    if (c * 64 >= len) return;

    extern __shared__ float sh[];
    float* uh_sh = sh;                 // [256 d][64 s]
    float* wq_sh = sh + 256 * 64;      // [8][256]
    float* v_sh  = wq_sh + 8 * 256;    // [256]

    const int tid = threadIdx.x;
    const int lane = tid & 31;
    const int warp = tid >> 5;

    {
        // wq tile: fold 4 split-K partials
        const int base = (b * TT + t0) * MD;
        for (int i = tid; i < (8 * 256) / 4; i += 256) {
            float4 r0 = *(const float4*)&g_wqp[0][base + i * 4];
            float4 r1 = *(const float4*)&g_wqp[1][base + i * 4];
            float4 r2 = *(const float4*)&g_wqp[2][base + i * 4];
            float4 r3 = *(const float4*)&g_wqp[3][base + i * 4];
            *(float4*)&wq_sh[i * 4] = make_float4(
                r0.x + r1.x + r2.x + r3.x, r0.y + r1.y + r2.y + r3.y,
                r0.z + r1.z + r2.z + r3.z, r0.w + r1.w + r2.w + r3.w);
        }
        if (tid < 64)
            *(float4*)&v_sh[tid * 4] = *(const float4*)&v[tid * 4];
        // uh chunk: [256 d][64 s]; fold 2 partials + bias bc[d]
        const int ubase = b * (MD * SS) + c * 64;
        for (int i = tid; i < 256 * 16; i += 256) {
            const int d = i >> 4, g = i & 15;
            float4 x = *(const float4*)&g_uhtp[0][ubase + d * SS + g * 4];
            float4 y = *(const float4*)&g_uhtp[1][ubase + d * SS + g * 4];
            const float bb = bc[d];
            *(float4*)&uh_sh[d * 64 + g * 4] = make_float4(
                x.x + y.x + bb, x.y + y.y + bb,
                x.z + y.z + bb, x.w + y.w + bb);
        }
    }
    __syncthreads();

    // warp handles t row t0+warp; lane handles s pair lane*2
    const float* wq0 = wq_sh + warp * 256;
    const int sl = lane * 2;
    float2 a0 = make_float2(0.f, 0.f);
#pragma unroll 8
    for (int d = 0; d < 256; d++) {
        float2 u = *(float2*)&uh_sh[d * 64 + sl];
        float w0 = wq0[d], vd = v_sh[d];
        a0.x += vd * tanhap(u.x + w0);
        a0.y += vd * tanhap(u.y + w0);
    }
    *(float2*)&pa[(b * TT + t0 + warp) * SS + c * 64 + sl] = a0;
}

// ---------------------------------------------------------------------------
// softmax_kernel: warp per t-row, 8 rows/block, 256 blocks.
// ---------------------------------------------------------------------------
__global__ __launch_bounds__(256) void softmax_kernel(
    const int* __restrict__ mem_masks, float* __restrict__ pa)
{
    const int lane = threadIdx.x & 31;
    const int warp = threadIdx.x >> 5;
    const int row = blockIdx.x * 8 + warp;   // 0..2047
    const int b = row >> 9;
    const int len = mem_masks[b];
    float* prow = pa + row * SS;
    const float NEG = -CUDART_INF_F;

    float vals[16];
    float mx = NEG;
#pragma unroll
    for (int k = 0; k < 16; k++) {
        const int s = lane + k * 32;
        const float val = (s < len) ? prow[s] : NEG;
        vals[k] = val;
        mx = fmaxf(mx, val);
    }
#pragma unroll
    for (int o = 16; o; o >>= 1) mx = fmaxf(mx, __shfl_xor_sync(~0u, mx, o));
    float sum = 0.f;
#pragma unroll
    for (int k = 0; k < 16; k++) {
        const int s = lane + k * 32;
        const float e = (s < len) ? __expf(vals[k] - mx) : 0.f;
        vals[k] = e;
        sum += e;
    }
#pragma unroll
    for (int o = 16; o; o >>= 1) sum += __shfl_xor_sync(~0u, sum, o);
    const float inv = 1.0f / sum;
#pragma unroll
    for (int k = 0; k < 16; k++) prow[lane + k * 32] = vals[k] * inv;
}

// ---------------------------------------------------------------------------
// ctx_kernel: split-K=2 partials of c[t][m] = sum_s P[t][s]*mems[b][s][m].
// 64x64 tile, 256 thr, 4x4/thread. Grid (4,8,8)=256 blocks.
// ---------------------------------------------------------------------------
__global__ __launch_bounds__(256) void ctx_kernel(
    const float* __restrict__ mems, const int* __restrict__ mem_masks,
    const float* __restrict__ pa)
{
    __shared__ float As[8][68];   // [k][t]
    __shared__ float Bs[8][68];   // [k][m]

    const int b = blockIdx.z >> 1;
    const int kc = blockIdx.z & 1;
    const int t0 = blockIdx.y * 64;
    const int n0b = blockIdx.x * 64;
    const int len = mem_masks[b];
    const int s0 = kc * 256;
    int lc = len - s0;
    if (lc > 256) lc = 256;
    const int NT = (lc > 0) ? ((lc + 7) >> 3) : 0;

    const int tid = threadIdx.x;
    const int lr = tid >> 2;
    const int lk = (tid & 3) * 2;
    const int bk = tid >> 5;
    const int bm = (tid & 31) * 2;
    const int tx = tid & 15, ty = tid >> 4;
    const int n0 = tx * 4, m0 = ty * 4;

    float acc[4][4];
#pragma unroll
    for (int i = 0; i < 4; i++)
#pragma unroll
        for (int j = 0; j < 4; j++) acc[i][j] = 0.f;

    if (NT > 0) {
        const float* P  = pa + (b * TT + t0 + lr) * SS + s0 + lk;
        const float* Mb = mems + b * (SS * MD) + (s0 + bk) * MD + n0b + bm;

        float2 a2 = *(const float2*)P;
        float2 b2 = *(const float2*)Mb;

        for (int kt = 0; kt < NT; kt++) {
            As[lk][lr] = a2.x; As[lk + 1][lr] = a2.y;
            *(float2*)&Bs[bk][bm] = b2;
            __syncthreads();
            if (kt + 1 < NT) {
                a2 = *(const float2*)(P + (kt + 1) * 8);
                b2 = *(const float2*)(Mb + (kt + 1) * 8 * MD);
            }
#pragma unroll
            for (int k = 0; k < 8; k++) {
                float4 af = *(const float4*)&As[k][m0];
                float4 bf = *(const float4*)&Bs[k][n0];
                float am[4] = {af.x, af.y, af.z, af.w};
                float bb[4] = {bf.x, bf.y, bf.z, bf.w};
#pragma unroll
                for (int i = 0; i < 4; i++)
#pragma unroll
                    for (int j = 0; j < 4; j++) acc[i][j] += am[i] * bb[j];
            }
            __syncthreads();
        }
    }

    float* dst = g_ctxp[kc];
#pragma unroll
    for (int i = 0; i < 4; i++) {
        float4 r = make_float4(acc[i][0], acc[i][1], acc[i][2], acc[i][3]);
        *(float4*)&dst[(b * TT + t0 + m0 + i) * MD + n0b + n0] = r;
    }
}

// ---------------------------------------------------------------------------
// out_kernel: split-K=3 partials of concat(c,inputs) @ Wout^T.
// kc=0 reads ctx as p0+p1 (folds ctx reduce); kc=1/2 read inputs halves.
// 128x64 tile, 256 threads, 8x4. Grid (8,16,3)=384 blocks.
// ---------------------------------------------------------------------------
__global__ __launch_bounds__(256) void out_kernel(
    const float* __restrict__ inputs, const float* __restrict__ Wout)
{
    __shared__ float As[8][132];
    __shared__ float Bs[8][68];

    const int tid = threadIdx.x;
    const int bm = blockIdx.y * 128;
    const int bn = blockIdx.x * 64;
    const int kc = blockIdx.z;
    const int lrA = tid >> 1;
    const int lcA = (tid & 1) * 4;
    const int tx = tid & 15, ty = tid >> 4;
    const int n0 = tx * 4, m0 = ty * 8;

    const float* p0row = g_ctxp[0] + (bm + lrA) * MD;
    const float* p1row = g_ctxp[1] + (bm + lrA) * MD;
    const float* irow  = inputs + (bm + lrA) * IND + (kc - 1) * 256;
    const float* Wbase = Wout + (bn + lrA) * 768 + kc * 256;

    auto fetchA = [&](int k0) -> float4 {
        if (kc == 0) {
            float4 x = *(const float4*)(p0row + k0 + lcA);
            float4 y = *(const float4*)(p1row + k0 + lcA);
            return make_float4(x.x + y.x, x.y + y.y, x.z + y.z, x.w + y.w);
        }
        return *(const float4*)(irow + k0 + lcA);
    };

    float acc[8][4];
#pragma unroll
    for (int i = 0; i < 8; i++)
#pragma unroll
        for (int j = 0; j < 4; j++) acc[i][j] = 0.f;

    float4 a4 = fetchA(0);
    float4 b4 = make_float4(0.f, 0.f, 0.f, 0.f);
    if (tid < 128) b4 = *(const float4*)(Wbase + lcA);

    for (int k0 = 0; k0 < 256; k0 += 8) {
        As[lcA + 0][lrA] = a4.x; As[lcA + 1][lrA] = a4.y;
        As[lcA + 2][lrA] = a4.z; As[lcA + 3][lrA] = a4.w;
        if (tid < 128) {
            Bs[lcA + 0][lrA] = b4.x; Bs[lcA + 1][lrA] = b4.y;
            Bs[lcA + 2][lrA] = b4.z; Bs[lcA + 3][lrA] = b4.w;
        }
        __syncthreads();
        const int kn = k0 + 8;
        if (kn < 256) {
            a4 = fetchA(kn);
            if (tid < 128) b4 = *(const float4*)(Wbase + kn + lcA);
        }
#pragma unroll
        for (int kk = 0; kk < 8; kk++) {
            float4 x0 = *(const float4*)&As[kk][m0];
            float4 x1 = *(const float4*)&As[kk][m0 + 4];
            float4 y  = *(const float4*)&Bs[kk][n0];
            float am[8] = {x0.x, x0.y, x0.z, x0.w, x1.x, x1.y, x1.z, x1.w};
            float bb[4] = {y.x, y.y, y.z, y.w};
#pragma unroll
            for (int i = 0; i < 8; i++)
#pragma unroll
                for (int j = 0; j < 4; j++) acc[i][j] += am[i] * bb[j];
        }
        __syncthreads();
    }

    float* dst = g_outp[kc];
#pragma unroll
    for (int i = 0; i < 8; i++) {
        float4 r = make_float4(acc[i][0], acc[i][1], acc[i][2], acc[i][3]);
        *(float4*)&dst[(bm + m0 + i) * IND + bn + n0] = r;
    }
}

// ---------------------------------------------------------------------------
// reduce_kernel: out = outp0 + outp1 + outp2 + bias
// ---------------------------------------------------------------------------
__global__ __launch_bounds__(256) void reduce_kernel(
    const float* __restrict__ bout, float* __restrict__ out)
{
    const int idx = blockIdx.x * 256 + threadIdx.x;   // float4 index
    const int e = idx * 4;
    float4 p0 = *(const float4*)&g_outp[0][e];
    float4 p1 = *(const float4*)&g_outp[1][e];
    float4 p2 = *(const float4*)&g_outp[2][e];
    float4 bb = *(const float4*)&bout[e & 511];
    float4 r = make_float4(p0.x + p1.x + p2.x + bb.x,
                           p0.y + p1.y + p2.y + bb.y,
                           p0.z + p1.z + p2.z + bb.z,
                           p0.w + p1.w + p2.w + bb.w);
    *(float4*)&out[e] = r;
}

// ---------------------------------------------------------------------------
extern "C" void kernel_launch(void* const* d_in, const int* in_sizes, int n_in,
                              void* d_out, int out_size)
{
    const float* inputs    = (const float*)d_in[0];
    const float* mems      = (const float*)d_in[1];
    const int*   mem_masks = (const int*)d_in[2];
    const float* Wq        = (const float*)d_in[3];
    const float* Wc        = (const float*)d_in[4];
    const float* bc        = (const float*)d_in[5];
    const float* v         = (const float*)d_in[6];
    const float* Wout      = (const float*)d_in[7];
    const float* bout      = (const float*)d_in[8];

    float* out = (float*)d_out;
    float* pa;
    if (out_size >= BN * TT * IND + BN * TT * SS) {
        pa = out + BN * TT * IND;  // align written in-place in the output
    } else {
        cudaGetSymbolAddress((void**)&pa, g_align_scratch);
    }

    const size_t SMEM_ALIGN = (size_t)(256 * 64 + 8 * 256 + 256) * sizeof(float);
    cudaFuncSetAttribute(align_kernel,
                         cudaFuncAttributeMaxDynamicSharedMemorySize, (int)SMEM_ALIGN);

    proj_kernel<<<dim3(4, 16, 6), 256>>>(inputs, mems, Wq, Wc);
    align_kernel<<<dim3(8, 64, 4), 256, SMEM_ALIGN>>>(mem_masks, v, bc, pa);
    softmax_kernel<<<256, 256>>>(mem_masks, pa);
    ctx_kernel<<<dim3(4, 8, 8), 256>>>(mems, mem_masks, pa);
    out_kernel<<<dim3(8, 16, 3), 256>>>(inputs, Wout);
    reduce_kernel<<<(BN * TT * IND) / (256 * 4), 256>>>(bout, out);
}

// round 12
// speedup vs baseline: 1.0728x; 1.0728x over previous
#include <cuda_runtime.h>
#include <cuda_bf16.h>
#include <math_constants.h>
#include <cstdint>

#define BN 4
#define TT 512
#define SS 512
#define IND 512
#define MD 256

// Scratch (allocation-free rule: __device__ globals)
__device__ float g_wq[BN * TT * MD];            // [b*T+t][d]
__device__ float g_uht[BN * MD * SS];           // [b][d][s]  (transposed uh)
__device__ float g_ctxp[2][BN * TT * MD];       // ctx split-K partials
__device__ float g_align_scratch[BN * TT * SS];
// bf16-split packed operands for tensor-core out GEMM.
// Layout per row: 384 k-pairs, each pair = 2 u32: [hi(k),hi(k+1)] then [lo(k),lo(k+1)]
__device__ uint32_t g_apk[BN * TT * 768];       // A = concat(c, inputs)
__device__ uint32_t g_wpk[IND * 768];           // Wout

__device__ __forceinline__ float tanhap(float x) {
    float y;
    asm("tanh.approx.f32 %0, %1;" : "=f"(y) : "f"(x));
    return y;
}

__device__ __forceinline__ uint32_t pack_bf2(float x0, float x1) {
    __nv_bfloat162 h = __floats2bfloat162_rn(x0, x1);
    return *reinterpret_cast<uint32_t*>(&h);
}

// ---------------------------------------------------------------------------
// proj_kernel (R10): z=0 -> g_wq = inputs @ Wq^T   (K=512)
//                    z=1 -> g_uht[b][n][s] = mems @ Wc^T + bc (transposed)
// ---------------------------------------------------------------------------
__global__ __launch_bounds__(256) void proj_kernel(
    const float* __restrict__ inputs, const float* __restrict__ mems,
    const float* __restrict__ Wq, const float* __restrict__ Wc,
    const float* __restrict__ bc)
{
    const int z = blockIdx.z;
    const float* A  = z ? mems : inputs;
    const float* Bm = z ? Wc : Wq;
    const int K = z ? MD : IND;

    __shared__ float As[8][132];
    __shared__ float Bs[8][68];

    const int tid = threadIdx.x;
    const int bm = blockIdx.y * 128;
    const int bn = blockIdx.x * 64;
    const int lrA = tid >> 1;
    const int lcA = (tid & 1) * 4;
    const int tx = tid & 15, ty = tid >> 4;
    const int n0 = tx * 4, m0 = ty * 8;

    float acc[8][4];
#pragma unroll
    for (int i = 0; i < 8; i++)
#pragma unroll
        for (int j = 0; j < 4; j++) acc[i][j] = 0.f;

    float4 a4 = *(const float4*)(A + (bm + lrA) * K + lcA);
    float4 b4 = make_float4(0.f, 0.f, 0.f, 0.f);
    if (tid < 128) b4 = *(const float4*)(Bm + (bn + lrA) * K + lcA);

    for (int k0 = 0; k0 < K; k0 += 8) {
        As[lcA + 0][lrA] = a4.x; As[lcA + 1][lrA] = a4.y;
        As[lcA + 2][lrA] = a4.z; As[lcA + 3][lrA] = a4.w;
        if (tid < 128) {
            Bs[lcA + 0][lrA] = b4.x; Bs[lcA + 1][lrA] = b4.y;
            Bs[lcA + 2][lrA] = b4.z; Bs[lcA + 3][lrA] = b4.w;
        }
        __syncthreads();
        const int kn = k0 + 8;
        if (kn < K) {
            a4 = *(const float4*)(A + (bm + lrA) * K + kn + lcA);
            if (tid < 128) b4 = *(const float4*)(Bm + (bn + lrA) * K + kn + lcA);
        }
#pragma unroll
        for (int kk = 0; kk < 8; kk++) {
            float4 x0 = *(const float4*)&As[kk][m0];
            float4 x1 = *(const float4*)&As[kk][m0 + 4];
            float4 y  = *(const float4*)&Bs[kk][n0];
            float am[8] = {x0.x, x0.y, x0.z, x0.w, x1.x, x1.y, x1.z, x1.w};
            float bb[4] = {y.x, y.y, y.z, y.w};
#pragma unroll
            for (int i = 0; i < 8; i++)
#pragma unroll
                for (int j = 0; j < 4; j++) acc[i][j] += am[i] * bb[j];
        }
        __syncthreads();
    }

    if (z == 0) {
#pragma unroll
        for (int i = 0; i < 8; i++) {
            float4 r = make_float4(acc[i][0], acc[i][1], acc[i][2], acc[i][3]);
            *(float4*)&g_wq[(bm + m0 + i) * MD + bn + n0] = r;
        }
    } else {
        float bb[4];
#pragma unroll
        for (int j = 0; j < 4; j++) bb[j] = bc[bn + n0 + j];
#pragma unroll
        for (int i = 0; i < 8; i++) {
            const int m = bm + m0 + i;
            const int b = m >> 9;
            const int s = m & 511;
#pragma unroll
            for (int j = 0; j < 4; j++)
                g_uht[b * (MD * SS) + (bn + n0 + j) * SS + s] = acc[i][j] + bb[j];
        }
    }
}

// ---------------------------------------------------------------------------
// align_kernel (R10): 64-s chunks, 16-t tiles, smem ~82KB.
// ---------------------------------------------------------------------------
__global__ __launch_bounds__(256) void align_kernel(
    const int* __restrict__ mem_masks, const float* __restrict__ v,
    float* __restrict__ pa)
{
    const int b = blockIdx.z;
    const int t0 = blockIdx.y * 16;
    const int c = blockIdx.x;
    const int len = mem_masks[b];
    if (c * 64 >= len) return;

    extern __shared__ float sh[];
    float* uh_sh = sh;                 // [256 d][64 s]
    float* wq_sh = sh + 256 * 64;      // [16][256]
    float* v_sh  = wq_sh + 16 * 256;   // [256]

    const int tid = threadIdx.x;
    const int lane = tid & 31;
    const int warp = tid >> 5;

    {
        const float* src = g_wq + (b * TT + t0) * MD;
        for (int i = tid; i < (16 * 256) / 4; i += 256)
            *(float4*)&wq_sh[i * 4] = *(const float4*)&src[i * 4];
        if (tid < 64)
            *(float4*)&v_sh[tid * 4] = *(const float4*)&v[tid * 4];
        const float* usrc = g_uht + b * (MD * SS) + c * 64;
        for (int i = tid; i < 256 * 16; i += 256) {
            const int d = i >> 4, g = i & 15;
            *(float4*)&uh_sh[d * 64 + g * 4] =
                *(const float4*)&usrc[d * SS + g * 4];
        }
    }
    __syncthreads();

    const int ta = warp * 2;
    const float* wq0 = wq_sh + ta * 256;
    const float* wq1 = wq0 + 256;
    const int sl = lane * 2;
    float2 a0 = make_float2(0.f, 0.f);
    float2 a1 = make_float2(0.f, 0.f);
#pragma unroll 8
    for (int d = 0; d < 256; d++) {
        float2 u = *(float2*)&uh_sh[d * 64 + sl];
        float w0 = wq0[d], w1 = wq1[d], vd = v_sh[d];
        a0.x += vd * tanhap(u.x + w0);
        a0.y += vd * tanhap(u.y + w0);
        a1.x += vd * tanhap(u.x + w1);
        a1.y += vd * tanhap(u.y + w1);
    }
    const int sg = c * 64 + sl;
    *(float2*)&pa[(b * TT + t0 + ta) * SS + sg] = a0;
    *(float2*)&pa[(b * TT + t0 + ta + 1) * SS + sg] = a1;
}

// ---------------------------------------------------------------------------
// softmax_kernel: warp per t-row.
// ---------------------------------------------------------------------------
__global__ __launch_bounds__(256) void softmax_kernel(
    const int* __restrict__ mem_masks, float* __restrict__ pa)
{
    const int lane = threadIdx.x & 31;
    const int warp = threadIdx.x >> 5;
    const int row = blockIdx.x * 8 + warp;
    const int b = row >> 9;
    const int len = mem_masks[b];
    float* prow = pa + row * SS;
    const float NEG = -CUDART_INF_F;

    float vals[16];
    float mx = NEG;
#pragma unroll
    for (int k = 0; k < 16; k++) {
        const int s = lane + k * 32;
        const float val = (s < len) ? prow[s] : NEG;
        vals[k] = val;
        mx = fmaxf(mx, val);
    }
#pragma unroll
    for (int o = 16; o; o >>= 1) mx = fmaxf(mx, __shfl_xor_sync(~0u, mx, o));
    float sum = 0.f;
#pragma unroll
    for (int k = 0; k < 16; k++) {
        const int s = lane + k * 32;
        const float e = (s < len) ? __expf(vals[k] - mx) : 0.f;
        vals[k] = e;
        sum += e;
    }
#pragma unroll
    for (int o = 16; o; o >>= 1) sum += __shfl_xor_sync(~0u, sum, o);
    const float inv = 1.0f / sum;
#pragma unroll
    for (int k = 0; k < 16; k++) prow[lane + k * 32] = vals[k] * inv;
}

// ---------------------------------------------------------------------------
// ctx_kernel (R10): split-K=2 partials. Grid (4,8,8)=256 blocks.
// ---------------------------------------------------------------------------
__global__ __launch_bounds__(256) void ctx_kernel(
    const float* __restrict__ mems, const int* __restrict__ mem_masks,
    const float* __restrict__ pa)
{
    __shared__ float As[8][68];
    __shared__ float Bs[8][68];

    const int b = blockIdx.z >> 1;
    const int kc = blockIdx.z & 1;
    const int t0 = blockIdx.y * 64;
    const int n0b = blockIdx.x * 64;
    const int len = mem_masks[b];
    const int s0 = kc * 256;
    int lc = len - s0;
    if (lc > 256) lc = 256;
    const int NT = (lc > 0) ? ((lc + 7) >> 3) : 0;

    const int tid = threadIdx.x;
    const int lr = tid >> 2;
    const int lk = (tid & 3) * 2;
    const int bk = tid >> 5;
    const int bm = (tid & 31) * 2;
    const int tx = tid & 15, ty = tid >> 4;
    const int n0 = tx * 4, m0 = ty * 4;

    float acc[4][4];
#pragma unroll
    for (int i = 0; i < 4; i++)
#pragma unroll
        for (int j = 0; j < 4; j++) acc[i][j] = 0.f;

    if (NT > 0) {
        const float* P  = pa + (b * TT + t0 + lr) * SS + s0 + lk;
        const float* Mb = mems + b * (SS * MD) + (s0 + bk) * MD + n0b + bm;

        float2 a2 = *(const float2*)P;
        float2 b2 = *(const float2*)Mb;

        for (int kt = 0; kt < NT; kt++) {
            As[lk][lr] = a2.x; As[lk + 1][lr] = a2.y;
            *(float2*)&Bs[bk][bm] = b2;
            __syncthreads();
            if (kt + 1 < NT) {
                a2 = *(const float2*)(P + (kt + 1) * 8);
                b2 = *(const float2*)(Mb + (kt + 1) * 8 * MD);
            }
#pragma unroll
            for (int k = 0; k < 8; k++) {
                float4 af = *(const float4*)&As[k][m0];
                float4 bf = *(const float4*)&Bs[k][n0];
                float am[4] = {af.x, af.y, af.z, af.w};
                float bb[4] = {bf.x, bf.y, bf.z, bf.w};
#pragma unroll
                for (int i = 0; i < 4; i++)
#pragma unroll
                    for (int j = 0; j < 4; j++) acc[i][j] += am[i] * bb[j];
            }
            __syncthreads();
        }
    }

    float* dst = g_ctxp[kc];
#pragma unroll
    for (int i = 0; i < 4; i++) {
        float4 r = make_float4(acc[i][0], acc[i][1], acc[i][2], acc[i][3]);
        *(float4*)&dst[(b * TT + t0 + m0 + i) * MD + n0b + n0] = r;
    }
}

// ---------------------------------------------------------------------------
// cvt_w: Wout fp32 -> packed bf16 hi/lo pairs. One thread per k-pair.
// ---------------------------------------------------------------------------
__global__ __launch_bounds__(256) void cvt_w(const float* __restrict__ Wout)
{
    const int idx = blockIdx.x * 256 + threadIdx.x;   // 512*384
    const int row = idx / 384, p = idx % 384;
    const float x0 = Wout[row * 768 + 2 * p];
    const float x1 = Wout[row * 768 + 2 * p + 1];
    const float h0 = __bfloat162float(__float2bfloat16_rn(x0));
    const float h1 = __bfloat162float(__float2bfloat16_rn(x1));
    g_wpk[row * 768 + 2 * p]     = pack_bf2(h0, h1);
    g_wpk[row * 768 + 2 * p + 1] = pack_bf2(x0 - h0, x1 - h1);
}

// ---------------------------------------------------------------------------
// cvt_in: inputs fp32 -> packed A k-region [256,768).
// ---------------------------------------------------------------------------
__global__ __launch_bounds__(256) void cvt_in(const float* __restrict__ inputs)
{
    const int idx = blockIdx.x * 256 + threadIdx.x;   // 2048*256
    const int row = idx >> 8, q = idx & 255;
    const float x0 = inputs[row * 512 + 2 * q];
    const float x1 = inputs[row * 512 + 2 * q + 1];
    const float h0 = __bfloat162float(__float2bfloat16_rn(x0));
    const float h1 = __bfloat162float(__float2bfloat16_rn(x1));
    const int base = row * 768 + 256 + 2 * q;   // pair index 128+q
    g_apk[base]     = pack_bf2(h0, h1);
    g_apk[base + 1] = pack_bf2(x0 - h0, x1 - h1);
}

// ---------------------------------------------------------------------------
// cvt_c: fold ctx partials + convert -> packed A k-region [0,256).
// ---------------------------------------------------------------------------
__global__ __launch_bounds__(256) void cvt_c()
{
    const int idx = blockIdx.x * 256 + threadIdx.x;   // 2048*128
    const int row = idx >> 7, q = idx & 127;
    const int e = row * 256 + 2 * q;
    const float x0 = g_ctxp[0][e] + g_ctxp[1][e];
    const float x1 = g_ctxp[0][e + 1] + g_ctxp[1][e + 1];
    const float h0 = __bfloat162float(__float2bfloat16_rn(x0));
    const float h1 = __bfloat162float(__float2bfloat16_rn(x1));
    const int base = row * 768 + 2 * q;
    g_apk[base]     = pack_bf2(h0, h1);
    g_apk[base + 1] = pack_bf2(x0 - h0, x1 - h1);
}

// ---------------------------------------------------------------------------
// out_mma: attn_h = A @ Wout^T + bout via bf16-split mma.sync (3 products:
// AhBh + AlBh + AhBl; fp32 accumulate). Block 128m x 64n, 256 thr (8 warps,
// 4m x 2n; warp tile 32x32). K=768, 48 k16 iters. Operands pre-packed in
// g_apk/g_wpk — no cvt in the mainloop. smem pitch 20 u32 (conflict-free
// LDS.64 frag loads). Grid (8,16)=128 blocks.
// ---------------------------------------------------------------------------
__global__ __launch_bounds__(256) void out_mma(
    const float* __restrict__ bout, float* __restrict__ out)
{
    __shared__ uint32_t Ash[2][128 * 20];
    __shared__ uint32_t Bsh[2][64 * 20];

    const int tid = threadIdx.x;
    const int lane = tid & 31;
    const int warp = tid >> 5;
    const int wm = warp >> 1, wn = warp & 1;
    const int bm = blockIdx.y * 128;
    const int bn = blockIdx.x * 64;
    const int g = lane >> 2, t = lane & 3;

    float c[2][4][4];
#pragma unroll
    for (int m2 = 0; m2 < 2; m2++)
#pragma unroll
        for (int n2 = 0; n2 < 4; n2++)
#pragma unroll
            for (int q = 0; q < 4; q++) c[m2][n2][q] = 0.f;

    // copy index precompute: A tasks tid, tid+256; B task tid
    const int ar0 = tid >> 2, as0 = (tid & 3) * 4;
    const int ar1 = (tid + 256) >> 2, as1 = as0;   // same seg pattern
    const int br = tid >> 2, bs = (tid & 3) * 4;   // only tid<256 all used

    uint4 ra0, ra1, rb;
    auto ldTile = [&](int it) {
        const int ko = it * 16;
        ra0 = *(const uint4*)&g_apk[(bm + ar0) * 768 + ko + as0];
        ra1 = *(const uint4*)&g_apk[(bm + ar1) * 768 + ko + as1];
        rb  = *(const uint4*)&g_wpk[(bn + br) * 768 + ko + bs];
    };
    auto stTile = [&](int buf) {
        *(uint4*)&Ash[buf][ar0 * 20 + as0] = ra0;
        *(uint4*)&Ash[buf][ar1 * 20 + as1] = ra1;
        *(uint4*)&Bsh[buf][br * 20 + bs] = rb;
    };

    ldTile(0);
    stTile(0);
    __syncthreads();

    int buf = 0;
    for (int it = 0; it < 48; it++) {
        const bool more = (it + 1 < 48);
        if (more) ldTile(it + 1);

        const uint32_t* Ab = Ash[buf] + (wm * 32) * 20;
        const uint32_t* Bb = Bsh[buf] + (wn * 32) * 20;

        // A frags: [m2][0..3] = a0..a3, each (hi, lo)
        uint2 af[2][4];
#pragma unroll
        for (int m2 = 0; m2 < 2; m2++) {
            const int r0 = m2 * 16 + g;
            af[m2][0] = *(const uint2*)&Ab[r0 * 20 + t * 2];
            af[m2][1] = *(const uint2*)&Ab[(r0 + 8) * 20 + t * 2];
            af[m2][2] = *(const uint2*)&Ab[r0 * 20 + t * 2 + 8];
            af[m2][3] = *(const uint2*)&Ab[(r0 + 8) * 20 + t * 2 + 8];
        }
        // B frags: [n2][0..1] = b0, b1, each (hi, lo)
        uint2 bf[4][2];
#pragma unroll
        for (int n2 = 0; n2 < 4; n2++) {
            const int rn = n2 * 8 + g;
            bf[n2][0] = *(const uint2*)&Bb[rn * 20 + t * 2];
            bf[n2][1] = *(const uint2*)&Bb[rn * 20 + t * 2 + 8];
        }

#pragma unroll
        for (int m2 = 0; m2 < 2; m2++) {
#pragma unroll
            for (int n2 = 0; n2 < 4; n2++) {
                float* cc = c[m2][n2];
                // Ah * Bh
                asm volatile(
                    "mma.sync.aligned.m16n8k16.row.col.f32.bf16.bf16.f32 "
                    "{%0,%1,%2,%3},{%4,%5,%6,%7},{%8,%9},{%0,%1,%2,%3};"
                    : "+f"(cc[0]), "+f"(cc[1]), "+f"(cc[2]), "+f"(cc[3])
                    : "r"(af[m2][0].x), "r"(af[m2][1].x),
                      "r"(af[m2][2].x), "r"(af[m2][3].x),
                      "r"(bf[n2][0].x), "r"(bf[n2][1].x));
                // Al * Bh
                asm volatile(
                    "mma.sync.aligned.m16n8k16.row.col.f32.bf16.bf16.f32 "
                    "{%0,%1,%2,%3},{%4,%5,%6,%7},{%8,%9},{%0,%1,%2,%3};"
                    : "+f"(cc[0]), "+f"(cc[1]), "+f"(cc[2]), "+f"(cc[3])
                    : "r"(af[m2][0].y), "r"(af[m2][1].y),
                      "r"(af[m2][2].y), "r"(af[m2][3].y),
                      "r"(bf[n2][0].x), "r"(bf[n2][1].x));
                // Ah * Bl
                asm volatile(
                    "mma.sync.aligned.m16n8k16.row.col.f32.bf16.bf16.f32 "
                    "{%0,%1,%2,%3},{%4,%5,%6,%7},{%8,%9},{%0,%1,%2,%3};"
                    : "+f"(cc[0]), "+f"(cc[1]), "+f"(cc[2]), "+f"(cc[3])
                    : "r"(af[m2][0].x), "r"(af[m2][1].x),
                      "r"(af[m2][2].x), "r"(af[m2][3].x),
                      "r"(bf[n2][0].y), "r"(bf[n2][1].y));
            }
        }

        if (more) stTile(buf ^ 1);
        __syncthreads();
        buf ^= 1;
    }

    // Epilogue: c0:(g,2t) c1:(g,2t+1) c2:(g+8,2t) c3:(g+8,2t+1); + bias
#pragma unroll
    for (int m2 = 0; m2 < 2; m2++) {
        const int r0 = bm + wm * 32 + m2 * 16 + g;
#pragma unroll
        for (int n2 = 0; n2 < 4; n2++) {
            const int col = bn + wn * 32 + n2 * 8 + t * 2;
            const float2 bb = *(const float2*)&bout[col];
            float* cc = c[m2][n2];
            *(float2*)&out[r0 * IND + col] =
                make_float2(cc[0] + bb.x, cc[1] + bb.y);
            *(float2*)&out[(r0 + 8) * IND + col] =
                make_float2(cc[2] + bb.x, cc[3] + bb.y);
        }
    }
}

// ---------------------------------------------------------------------------
extern "C" void kernel_launch(void* const* d_in, const int* in_sizes, int n_in,
                              void* d_out, int out_size)
{
    const float* inputs    = (const float*)d_in[0];
    const float* mems      = (const float*)d_in[1];
    const int*   mem_masks = (const int*)d_in[2];
    const float* Wq        = (const float*)d_in[3];
    const float* Wc        = (const float*)d_in[4];
    const float* bc        = (const float*)d_in[5];
    const float* v         = (const float*)d_in[6];
    const float* Wout      = (const float*)d_in[7];
    const float* bout      = (const float*)d_in[8];

    float* out = (float*)d_out;
    float* pa;
    if (out_size >= BN * TT * IND + BN * TT * SS) {
        pa = out + BN * TT * IND;  // align written in-place in the output
    } else {
        cudaGetSymbolAddress((void**)&pa, g_align_scratch);
    }

    const size_t SMEM_ALIGN = (size_t)(256 * 64 + 16 * 256 + 256) * sizeof(float);
    cudaFuncSetAttribute(align_kernel,
                         cudaFuncAttributeMaxDynamicSharedMemorySize, (int)SMEM_ALIGN);

    // Independent conversions first (weights + inputs).
    cvt_w<<<768, 256>>>(Wout);
    cvt_in<<<2048, 256>>>(inputs);

    proj_kernel<<<dim3(4, 16, 2), 256>>>(inputs, mems, Wq, Wc, bc);
    align_kernel<<<dim3(8, 32, 4), 256, SMEM_ALIGN>>>(mem_masks, v, pa);
    softmax_kernel<<<256, 256>>>(mem_masks, pa);
    ctx_kernel<<<dim3(4, 8, 8), 256>>>(mems, mem_masks, pa);
    cvt_c<<<1024, 256>>>();
    out_mma<<<dim3(8, 16), 256>>>(bout, out);
}

// round 13
// speedup vs baseline: 1.1720x; 1.0925x over previous
#include <cuda_runtime.h>
#include <cuda_bf16.h>
#include <math_constants.h>
#include <cstdint>

#define BN 4
#define TT 512
#define SS 512
#define IND 512
#define MD 256

// Scratch (allocation-free rule: __device__ globals)
__device__ float g_wq[BN * TT * MD];            // [b*T+t][d]
__device__ float g_uht[BN * MD * SS];           // [b][d][s]  (transposed uh)
__device__ float g_ctxp[2][BN * TT * MD];       // ctx split-K partials
__device__ float g_align_scratch[BN * TT * SS];
// bf16-split packed operands (per element 1 u32; pair p -> u32 2p=hi, 2p+1=lo)
__device__ uint32_t g_apk[BN * TT * 768];       // A(out) = concat(c, inputs)
__device__ uint32_t g_wpk[IND * 768];           // Wout
__device__ uint32_t g_wqpk[MD * 512];           // Wq
__device__ uint32_t g_wcpk[MD * 256];           // Wc
__device__ uint32_t g_mpk[BN * SS * 256];       // mems  [row][k=m]  (proj A)
__device__ uint32_t g_mtpk[BN * 256 * 512];     // mems^T [b][m][k=s] (ctx B)
__device__ uint32_t g_ppk[BN * TT * 512];       // P probabilities [row][k=s]

__device__ __forceinline__ float tanhap(float x) {
    float y;
    asm("tanh.approx.f32 %0, %1;" : "=f"(y) : "f"(x));
    return y;
}

__device__ __forceinline__ uint32_t pack_bf2(float x0, float x1) {
    __nv_bfloat162 h = __floats2bfloat162_rn(x0, x1);
    return *reinterpret_cast<uint32_t*>(&h);
}

__device__ __forceinline__ void split2(float x0, float x1,
                                       uint32_t& hi, uint32_t& lo) {
    const float h0 = __bfloat162float(__float2bfloat16_rn(x0));
    const float h1 = __bfloat162float(__float2bfloat16_rn(x1));
    hi = pack_bf2(h0, h1);
    lo = pack_bf2(x0 - h0, x1 - h1);
}

__device__ __forceinline__ void mma_bf(float* cc,
    uint32_t a0, uint32_t a1, uint32_t a2, uint32_t a3,
    uint32_t b0, uint32_t b1)
{
    asm volatile(
        "mma.sync.aligned.m16n8k16.row.col.f32.bf16.bf16.f32 "
        "{%0,%1,%2,%3},{%4,%5,%6,%7},{%8,%9},{%0,%1,%2,%3};"
        : "+f"(cc[0]), "+f"(cc[1]), "+f"(cc[2]), "+f"(cc[3])
        : "r"(a0), "r"(a1), "r"(a2), "r"(a3), "r"(b0), "r"(b1));
}

// ---------------------------------------------------------------------------
// cvt_pre: ALL static packing in one launch (flat-index regions).
//  R0: Wout -> g_wpk      (196608 pairs)
//  R1: inputs -> g_apk[256:768)  (524288)
//  R2: Wq -> g_wqpk       (65536)
//  R3: Wc -> g_wcpk       (32768)
//  R4: mems -> g_mpk      (262144)
//  R5: mems^T -> g_mtpk   (262144)
// ---------------------------------------------------------------------------
__global__ __launch_bounds__(256) void cvt_pre(
    const float* __restrict__ inputs, const float* __restrict__ mems,
    const float* __restrict__ Wq, const float* __restrict__ Wc,
    const float* __restrict__ Wout)
{
    int idx = blockIdx.x * 256 + threadIdx.x;
    uint32_t hi, lo;
    if (idx < 196608) {                       // R0: Wout
        const int row = idx / 384, p = idx % 384;
        split2(Wout[row * 768 + 2 * p], Wout[row * 768 + 2 * p + 1], hi, lo);
        g_wpk[row * 768 + 2 * p] = hi;
        g_wpk[row * 768 + 2 * p + 1] = lo;
        return;
    }
    idx -= 196608;
    if (idx < 524288) {                       // R1: inputs
        const int row = idx >> 8, q = idx & 255;
        split2(inputs[row * 512 + 2 * q], inputs[row * 512 + 2 * q + 1], hi, lo);
        g_apk[row * 768 + 256 + 2 * q] = hi;
        g_apk[row * 768 + 256 + 2 * q + 1] = lo;
        return;
    }
    idx -= 524288;
    if (idx < 65536) {                        // R2: Wq
        const int row = idx >> 8, p = idx & 255;
        split2(Wq[row * 512 + 2 * p], Wq[row * 512 + 2 * p + 1], hi, lo);
        g_wqpk[row * 512 + 2 * p] = hi;
        g_wqpk[row * 512 + 2 * p + 1] = lo;
        return;
    }
    idx -= 65536;
    if (idx < 32768) {                        // R3: Wc
        const int row = idx >> 7, p = idx & 127;
        split2(Wc[row * 256 + 2 * p], Wc[row * 256 + 2 * p + 1], hi, lo);
        g_wcpk[row * 256 + 2 * p] = hi;
        g_wcpk[row * 256 + 2 * p + 1] = lo;
        return;
    }
    idx -= 32768;
    if (idx < 262144) {                       // R4: mems (proj A layout)
        const int row = idx >> 7, p = idx & 127;
        split2(mems[row * 256 + 2 * p], mems[row * 256 + 2 * p + 1], hi, lo);
        g_mpk[row * 256 + 2 * p] = hi;
        g_mpk[row * 256 + 2 * p + 1] = lo;
        return;
    }
    idx -= 262144;
    {                                         // R5: mems^T (ctx B layout)
        const int b = idx >> 16;
        const int m = (idx >> 8) & 255;
        const int p = idx & 255;
        const float x0 = mems[b * 131072 + (2 * p) * 256 + m];
        const float x1 = mems[b * 131072 + (2 * p + 1) * 256 + m];
        split2(x0, x1, hi, lo);
        g_mtpk[b * 131072 + m * 512 + 2 * p] = hi;
        g_mtpk[b * 131072 + m * 512 + 2 * p + 1] = lo;
    }
}

// ---------------------------------------------------------------------------
// proj_mma: bf16x3 tensor-core projections. Block 128m x 64n, 256 thr.
//  z=0: g_wq  = inputs @ Wq^T  (K=512, 32 iters; A = g_apk inputs region)
//  z=1: g_uht = (mems @ Wc^T + bc) transposed  (K=256, 16 iters)
// Grid (4,16,2)=128 blocks.
// ---------------------------------------------------------------------------
__global__ __launch_bounds__(256) void proj_mma(const float* __restrict__ bc)
{
    __shared__ uint32_t Ash[2][128 * 20];
    __shared__ uint32_t Bsh[2][64 * 20];

    const int tid = threadIdx.x;
    const int lane = tid & 31;
    const int warp = tid >> 5;
    const int wm = warp >> 1, wn = warp & 1;
    const int bm = blockIdx.y * 128;
    const int bn = blockIdx.x * 64;
    const int z = blockIdx.z;
    const int g = lane >> 2, t = lane & 3;

    const uint32_t* Abase = z ? g_mpk : (g_apk + 256);
    const int astr = z ? 256 : 768;
    const uint32_t* Bbase = z ? g_wcpk : g_wqpk;
    const int bstr = z ? 256 : 512;
    const int NIT = z ? 16 : 32;

    float c[2][4][4];
#pragma unroll
    for (int m2 = 0; m2 < 2; m2++)
#pragma unroll
        for (int n2 = 0; n2 < 4; n2++)
#pragma unroll
            for (int q = 0; q < 4; q++) c[m2][n2][q] = 0.f;

    const int ar0 = tid >> 2, as0 = (tid & 3) * 4;
    const int ar1 = ar0 + 64;
    const int br = tid >> 2, bs = as0;

    uint4 ra0, ra1, rb;
    auto ldTile = [&](int it) {
        const int ko = it * 16;
        ra0 = *(const uint4*)&Abase[(bm + ar0) * astr + ko + as0];
        ra1 = *(const uint4*)&Abase[(bm + ar1) * astr + ko + as0];
        rb  = *(const uint4*)&Bbase[(bn + br) * bstr + ko + bs];
    };
    auto stTile = [&](int buf) {
        *(uint4*)&Ash[buf][ar0 * 20 + as0] = ra0;
        *(uint4*)&Ash[buf][ar1 * 20 + as0] = ra1;
        *(uint4*)&Bsh[buf][br * 20 + bs] = rb;
    };

    ldTile(0);
    stTile(0);
    __syncthreads();

    int buf = 0;
    for (int it = 0; it < NIT; it++) {
        const bool more = (it + 1 < NIT);
        if (more) ldTile(it + 1);

        const uint32_t* Ab = Ash[buf] + (wm * 32) * 20;
        const uint32_t* Bb = Bsh[buf] + (wn * 32) * 20;

        uint2 af[2][4];
#pragma unroll
        for (int m2 = 0; m2 < 2; m2++) {
            const int r0 = m2 * 16 + g;
            af[m2][0] = *(const uint2*)&Ab[r0 * 20 + t * 2];
            af[m2][1] = *(const uint2*)&Ab[(r0 + 8) * 20 + t * 2];
            af[m2][2] = *(const uint2*)&Ab[r0 * 20 + t * 2 + 8];
            af[m2][3] = *(const uint2*)&Ab[(r0 + 8) * 20 + t * 2 + 8];
        }
        uint2 bf[4][2];
#pragma unroll
        for (int n2 = 0; n2 < 4; n2++) {
            const int rn = n2 * 8 + g;
            bf[n2][0] = *(const uint2*)&Bb[rn * 20 + t * 2];
            bf[n2][1] = *(const uint2*)&Bb[rn * 20 + t * 2 + 8];
        }

#pragma unroll
        for (int m2 = 0; m2 < 2; m2++)
#pragma unroll
            for (int n2 = 0; n2 < 4; n2++) {
                float* cc = c[m2][n2];
                mma_bf(cc, af[m2][0].x, af[m2][1].x, af[m2][2].x, af[m2][3].x,
                       bf[n2][0].x, bf[n2][1].x);
                mma_bf(cc, af[m2][0].y, af[m2][1].y, af[m2][2].y, af[m2][3].y,
                       bf[n2][0].x, bf[n2][1].x);
                mma_bf(cc, af[m2][0].x, af[m2][1].x, af[m2][2].x, af[m2][3].x,
                       bf[n2][0].y, bf[n2][1].y);
            }

        if (more) stTile(buf ^ 1);
        __syncthreads();
        buf ^= 1;
    }

    if (z == 0) {
#pragma unroll
        for (int m2 = 0; m2 < 2; m2++) {
            const int r0 = bm + wm * 32 + m2 * 16 + g;
#pragma unroll
            for (int n2 = 0; n2 < 4; n2++) {
                const int col = bn + wn * 32 + n2 * 8 + t * 2;
                float* cc = c[m2][n2];
                *(float2*)&g_wq[r0 * MD + col] = make_float2(cc[0], cc[1]);
                *(float2*)&g_wq[(r0 + 8) * MD + col] = make_float2(cc[2], cc[3]);
            }
        }
    } else {
        const int b_ = bm >> 9;
        float* base = g_uht + b_ * (MD * SS);
#pragma unroll
        for (int m2 = 0; m2 < 2; m2++) {
            const int r0 = bm + wm * 32 + m2 * 16 + g;
            const int s0 = r0 & 511, s1 = (r0 + 8) & 511;
#pragma unroll
            for (int n2 = 0; n2 < 4; n2++) {
                const int col = bn + wn * 32 + n2 * 8 + t * 2;
                const float b0v = bc[col], b1v = bc[col + 1];
                float* cc = c[m2][n2];
                base[col * SS + s0] = cc[0] + b0v;
                base[(col + 1) * SS + s0] = cc[1] + b1v;
                base[col * SS + s1] = cc[2] + b0v;
                base[(col + 1) * SS + s1] = cc[3] + b1v;
            }
        }
    }
}

// ---------------------------------------------------------------------------
// align_kernel (R10/R12, at MUFU roofline): 64-s chunks, 16-t tiles.
// ---------------------------------------------------------------------------
__global__ __launch_bounds__(256) void align_kernel(
    const int* __restrict__ mem_masks, const float* __restrict__ v,
    float* __restrict__ pa)
{
    const int b = blockIdx.z;
    const int t0 = blockIdx.y * 16;
    const int c = blockIdx.x;
    const int len = mem_masks[b];
    if (c * 64 >= len) return;

    extern __shared__ float sh[];
    float* uh_sh = sh;                 // [256 d][64 s]
    float* wq_sh = sh + 256 * 64;      // [16][256]
    float* v_sh  = wq_sh + 16 * 256;   // [256]

    const int tid = threadIdx.x;
    const int lane = tid & 31;
    const int warp = tid >> 5;

    {
        const float* src = g_wq + (b * TT + t0) * MD;
        for (int i = tid; i < (16 * 256) / 4; i += 256)
            *(float4*)&wq_sh[i * 4] = *(const float4*)&src[i * 4];
        if (tid < 64)
            *(float4*)&v_sh[tid * 4] = *(const float4*)&v[tid * 4];
        const float* usrc = g_uht + b * (MD * SS) + c * 64;
        for (int i = tid; i < 256 * 16; i += 256) {
            const int d = i >> 4, g = i & 15;
            *(float4*)&uh_sh[d * 64 + g * 4] =
                *(const float4*)&usrc[d * SS + g * 4];
        }
    }
    __syncthreads();

    const int ta = warp * 2;
    const float* wq0 = wq_sh + ta * 256;
    const float* wq1 = wq0 + 256;
    const int sl = lane * 2;
    float2 a0 = make_float2(0.f, 0.f);
    float2 a1 = make_float2(0.f, 0.f);
#pragma unroll 8
    for (int d = 0; d < 256; d++) {
        float2 u = *(float2*)&uh_sh[d * 64 + sl];
        float w0 = wq0[d], w1 = wq1[d], vd = v_sh[d];
        a0.x += vd * tanhap(u.x + w0);
        a0.y += vd * tanhap(u.y + w0);
        a1.x += vd * tanhap(u.x + w1);
        a1.y += vd * tanhap(u.y + w1);
    }
    const int sg = c * 64 + sl;
    *(float2*)&pa[(b * TT + t0 + ta) * SS + sg] = a0;
    *(float2*)&pa[(b * TT + t0 + ta + 1) * SS + sg] = a1;
}

// ---------------------------------------------------------------------------
// softmax_kernel: warp per t-row; writes fp32 probs to pa AND bf16-split
// packed probs to g_ppk (pairs assembled via shfl; even lanes store).
// ---------------------------------------------------------------------------
__global__ __launch_bounds__(256) void softmax_kernel(
    const int* __restrict__ mem_masks, float* __restrict__ pa)
{
    const int lane = threadIdx.x & 31;
    const int warp = threadIdx.x >> 5;
    const int row = blockIdx.x * 8 + warp;
    const int b = row >> 9;
    const int len = mem_masks[b];
    float* prow = pa + row * SS;
    const float NEG = -CUDART_INF_F;

    float vals[16];
    float mx = NEG;
#pragma unroll
    for (int k = 0; k < 16; k++) {
        const int s = lane + k * 32;
        const float val = (s < len) ? prow[s] : NEG;
        vals[k] = val;
        mx = fmaxf(mx, val);
    }
#pragma unroll
    for (int o = 16; o; o >>= 1) mx = fmaxf(mx, __shfl_xor_sync(~0u, mx, o));
    float sum = 0.f;
#pragma unroll
    for (int k = 0; k < 16; k++) {
        const int s = lane + k * 32;
        const float e = (s < len) ? __expf(vals[k] - mx) : 0.f;
        vals[k] = e;
        sum += e;
    }
#pragma unroll
    for (int o = 16; o; o >>= 1) sum += __shfl_xor_sync(~0u, sum, o);
    const float inv = 1.0f / sum;
#pragma unroll
    for (int k = 0; k < 16; k++) {
        const float p = vals[k] * inv;
        prow[lane + k * 32] = p;
        const float pp = __shfl_xor_sync(~0u, p, 1);   // partner prob
        if ((lane & 1) == 0) {
            uint32_t hi, lo;
            split2(p, pp, hi, lo);
            *(uint2*)&g_ppk[row * 512 + lane + k * 32] = make_uint2(hi, lo);
        }
    }
}

// ---------------------------------------------------------------------------
// ctx_mma: bf16x3 tensor-core context, split-K=2 over s (len-trimmed).
// C_b[t][m] = sum_s P[t][s] * memsT[m][s]. Block 128t x 64m, 256 thr.
// Grid (4 m-tiles, 4 t-tiles, b*2+kc)=128 blocks. Writes g_ctxp[kc]
// (zeros when chunk fully masked -> deterministic).
// ---------------------------------------------------------------------------
__global__ __launch_bounds__(256) void ctx_mma(const int* __restrict__ mem_masks)
{
    __shared__ uint32_t Ash[2][128 * 20];
    __shared__ uint32_t Bsh[2][64 * 20];

    const int tid = threadIdx.x;
    const int lane = tid & 31;
    const int warp = tid >> 5;
    const int wm = warp >> 1, wn = warp & 1;
    const int b = blockIdx.z >> 1;
    const int kc = blockIdx.z & 1;
    const int bm = blockIdx.y * 128;      // t within b
    const int bn = blockIdx.x * 64;       // m
    const int g = lane >> 2, t = lane & 3;

    const int len = mem_masks[b];
    int rem = len - kc * 256;
    if (rem > 256) rem = 256;
    const int NIT = (rem > 0) ? ((rem + 15) >> 4) : 0;

    const uint32_t* Abase = g_ppk + (b * TT) * 512 + kc * 256;
    const uint32_t* Bbase = g_mtpk + b * (256 * 512) + kc * 256;

    float c[2][4][4];
#pragma unroll
    for (int m2 = 0; m2 < 2; m2++)
#pragma unroll
        for (int n2 = 0; n2 < 4; n2++)
#pragma unroll
            for (int q = 0; q < 4; q++) c[m2][n2][q] = 0.f;

    const int ar0 = tid >> 2, as0 = (tid & 3) * 4;
    const int ar1 = ar0 + 64;
    const int br = tid >> 2, bs = as0;

    if (NIT > 0) {
        uint4 ra0, ra1, rb;
        auto ldTile = [&](int it) {
            const int ko = it * 16;
            ra0 = *(const uint4*)&Abase[(bm + ar0) * 512 + ko + as0];
            ra1 = *(const uint4*)&Abase[(bm + ar1) * 512 + ko + as0];
            rb  = *(const uint4*)&Bbase[(bn + br) * 512 + ko + bs];
        };
        auto stTile = [&](int buf) {
            *(uint4*)&Ash[buf][ar0 * 20 + as0] = ra0;
            *(uint4*)&Ash[buf][ar1 * 20 + as0] = ra1;
            *(uint4*)&Bsh[buf][br * 20 + bs] = rb;
        };

        ldTile(0);
        stTile(0);
        __syncthreads();

        int buf = 0;
        for (int it = 0; it < NIT; it++) {
            const bool more = (it + 1 < NIT);
            if (more) ldTile(it + 1);

            const uint32_t* Ab = Ash[buf] + (wm * 32) * 20;
            const uint32_t* Bb = Bsh[buf] + (wn * 32) * 20;

            uint2 af[2][4];
#pragma unroll
            for (int m2 = 0; m2 < 2; m2++) {
                const int r0 = m2 * 16 + g;
                af[m2][0] = *(const uint2*)&Ab[r0 * 20 + t * 2];
                af[m2][1] = *(const uint2*)&Ab[(r0 + 8) * 20 + t * 2];
                af[m2][2] = *(const uint2*)&Ab[r0 * 20 + t * 2 + 8];
                af[m2][3] = *(const uint2*)&Ab[(r0 + 8) * 20 + t * 2 + 8];
            }
            uint2 bf[4][2];
#pragma unroll
            for (int n2 = 0; n2 < 4; n2++) {
                const int rn = n2 * 8 + g;
                bf[n2][0] = *(const uint2*)&Bb[rn * 20 + t * 2];
                bf[n2][1] = *(const uint2*)&Bb[rn * 20 + t * 2 + 8];
            }

#pragma unroll
            for (int m2 = 0; m2 < 2; m2++)
#pragma unroll
                for (int n2 = 0; n2 < 4; n2++) {
                    float* cc = c[m2][n2];
                    mma_bf(cc, af[m2][0].x, af[m2][1].x, af[m2][2].x,
                           af[m2][3].x, bf[n2][0].x, bf[n2][1].x);
                    mma_bf(cc, af[m2][0].y, af[m2][1].y, af[m2][2].y,
                           af[m2][3].y, bf[n2][0].x, bf[n2][1].x);
                    mma_bf(cc, af[m2][0].x, af[m2][1].x, af[m2][2].x,
                           af[m2][3].x, bf[n2][0].y, bf[n2][1].y);
                }

            if (more) stTile(buf ^ 1);
            __syncthreads();
            buf ^= 1;
        }
    }

    float* dst = g_ctxp[kc];
#pragma unroll
    for (int m2 = 0; m2 < 2; m2++) {
        const int r0 = b * TT + bm + wm * 32 + m2 * 16 + g;
#pragma unroll
        for (int n2 = 0; n2 < 4; n2++) {
            const int col = bn + wn * 32 + n2 * 8 + t * 2;
            float* cc = c[m2][n2];
            *(float2*)&dst[r0 * MD + col] = make_float2(cc[0], cc[1]);
            *(float2*)&dst[(r0 + 8) * MD + col] = make_float2(cc[2], cc[3]);
        }
    }
}

// ---------------------------------------------------------------------------
// cvt_c: fold ctx partials + convert -> packed A k-region [0,256).
// ---------------------------------------------------------------------------
__global__ __launch_bounds__(256) void cvt_c()
{
    const int idx = blockIdx.x * 256 + threadIdx.x;   // 2048*128
    const int row = idx >> 7, q = idx & 127;
    const int e = row * 256 + 2 * q;
    const float x0 = g_ctxp[0][e] + g_ctxp[1][e];
    const float x1 = g_ctxp[0][e + 1] + g_ctxp[1][e + 1];
    uint32_t hi, lo;
    split2(x0, x1, hi, lo);
    const int base = row * 768 + 2 * q;
    g_apk[base] = hi;
    g_apk[base + 1] = lo;
}

// ---------------------------------------------------------------------------
// out_mma (R12, validated): attn_h = A @ Wout^T + bout via bf16x3 mma.
// Block 128m x 64n, 256 thr, K=768 (48 iters). Grid (8,16)=128 blocks.
// ---------------------------------------------------------------------------
__global__ __launch_bounds__(256) void out_mma(
    const float* __restrict__ bout, float* __restrict__ out)
{
    __shared__ uint32_t Ash[2][128 * 20];
    __shared__ uint32_t Bsh[2][64 * 20];

    const int tid = threadIdx.x;
    const int lane = tid & 31;
    const int warp = tid >> 5;
    const int wm = warp >> 1, wn = warp & 1;
    const int bm = blockIdx.y * 128;
    const int bn = blockIdx.x * 64;
    const int g = lane >> 2, t = lane & 3;

    float c[2][4][4];
#pragma unroll
    for (int m2 = 0; m2 < 2; m2++)
#pragma unroll
        for (int n2 = 0; n2 < 4; n2++)
#pragma unroll
            for (int q = 0; q < 4; q++) c[m2][n2][q] = 0.f;

    const int ar0 = tid >> 2, as0 = (tid & 3) * 4;
    const int ar1 = ar0 + 64;
    const int br = tid >> 2, bs = as0;

    uint4 ra0, ra1, rb;
    auto ldTile = [&](int it) {
        const int ko = it * 16;
        ra0 = *(const uint4*)&g_apk[(bm + ar0) * 768 + ko + as0];
        ra1 = *(const uint4*)&g_apk[(bm + ar1) * 768 + ko + as0];
        rb  = *(const uint4*)&g_wpk[(bn + br) * 768 + ko + bs];
    };
    auto stTile = [&](int buf) {
        *(uint4*)&Ash[buf][ar0 * 20 + as0] = ra0;
        *(uint4*)&Ash[buf][ar1 * 20 + as0] = ra1;
        *(uint4*)&Bsh[buf][br * 20 + bs] = rb;
    };

    ldTile(0);
    stTile(0);
    __syncthreads();

    int buf = 0;
    for (int it = 0; it < 48; it++) {
        const bool more = (it + 1 < 48);
        if (more) ldTile(it + 1);

        const uint32_t* Ab = Ash[buf] + (wm * 32) * 20;
        const uint32_t* Bb = Bsh[buf] + (wn * 32) * 20;

        uint2 af[2][4];
#pragma unroll
        for (int m2 = 0; m2 < 2; m2++) {
            const int r0 = m2 * 16 + g;
            af[m2][0] = *(const uint2*)&Ab[r0 * 20 + t * 2];
            af[m2][1] = *(const uint2*)&Ab[(r0 + 8) * 20 + t * 2];
            af[m2][2] = *(const uint2*)&Ab[r0 * 20 + t * 2 + 8];
            af[m2][3] = *(const uint2*)&Ab[(r0 + 8) * 20 + t * 2 + 8];
        }
        uint2 bf[4][2];
#pragma unroll
        for (int n2 = 0; n2 < 4; n2++) {
            const int rn = n2 * 8 + g;
            bf[n2][0] = *(const uint2*)&Bb[rn * 20 + t * 2];
            bf[n2][1] = *(const uint2*)&Bb[rn * 20 + t * 2 + 8];
        }

#pragma unroll
        for (int m2 = 0; m2 < 2; m2++)
#pragma unroll
            for (int n2 = 0; n2 < 4; n2++) {
                float* cc = c[m2][n2];
                mma_bf(cc, af[m2][0].x, af[m2][1].x, af[m2][2].x, af[m2][3].x,
                       bf[n2][0].x, bf[n2][1].x);
                mma_bf(cc, af[m2][0].y, af[m2][1].y, af[m2][2].y, af[m2][3].y,
                       bf[n2][0].x, bf[n2][1].x);
                mma_bf(cc, af[m2][0].x, af[m2][1].x, af[m2][2].x, af[m2][3].x,
                       bf[n2][0].y, bf[n2][1].y);
            }

        if (more) stTile(buf ^ 1);
        __syncthreads();
        buf ^= 1;
    }

#pragma unroll
    for (int m2 = 0; m2 < 2; m2++) {
        const int r0 = bm + wm * 32 + m2 * 16 + g;
#pragma unroll
        for (int n2 = 0; n2 < 4; n2++) {
            const int col = bn + wn * 32 + n2 * 8 + t * 2;
            const float2 bb = *(const float2*)&bout[col];
            float* cc = c[m2][n2];
            *(float2*)&out[r0 * IND + col] =
                make_float2(cc[0] + bb.x, cc[1] + bb.y);
            *(float2*)&out[(r0 + 8) * IND + col] =
                make_float2(cc[2] + bb.x, cc[3] + bb.y);
        }
    }
}

// ---------------------------------------------------------------------------
extern "C" void kernel_launch(void* const* d_in, const int* in_sizes, int n_in,
                              void* d_out, int out_size)
{
    const float* inputs    = (const float*)d_in[0];
    const float* mems      = (const float*)d_in[1];
    const int*   mem_masks = (const int*)d_in[2];
    const float* Wq        = (const float*)d_in[3];
    const float* Wc        = (const float*)d_in[4];
    const float* bc        = (const float*)d_in[5];
    const float* v         = (const float*)d_in[6];
    const float* Wout      = (const float*)d_in[7];
    const float* bout      = (const float*)d_in[8];

    float* out = (float*)d_out;
    float* pa;
    if (out_size >= BN * TT * IND + BN * TT * SS) {
        pa = out + BN * TT * IND;  // align written in-place in the output
    } else {
        cudaGetSymbolAddress((void**)&pa, g_align_scratch);
    }

    const size_t SMEM_ALIGN = (size_t)(256 * 64 + 16 * 256 + 256) * sizeof(float);
    cudaFuncSetAttribute(align_kernel,
                         cudaFuncAttributeMaxDynamicSharedMemorySize, (int)SMEM_ALIGN);

    cvt_pre<<<5248, 256>>>(inputs, mems, Wq, Wc, Wout);
    proj_mma<<<dim3(4, 16, 2), 256>>>(bc);
    align_kernel<<<dim3(8, 32, 4), 256, SMEM_ALIGN>>>(mem_masks, v, pa);
    softmax_kernel<<<256, 256>>>(mem_masks, pa);
    ctx_mma<<<dim3(4, 4, 8), 256>>>(mem_masks);
    cvt_c<<<1024, 256>>>();
    out_mma<<<dim3(8, 16), 256>>>(bout, out);
}

// round 14
// speedup vs baseline: 1.2207x; 1.0415x over previous
#include <cuda_runtime.h>
#include <cuda_bf16.h>
#include <math_constants.h>
#include <cstdint>

#define BN 4
#define TT 512
#define SS 512
#define IND 512
#define MD 256

// Scratch (allocation-free rule: __device__ globals)
__device__ float g_wq[BN * TT * MD];            // [b*T+t][d]
__device__ float g_uht[BN * MD * SS];           // [b][d][s]  (transposed uh)
__device__ float g_ctxp[2][BN * TT * MD];       // ctx split-K partials
__device__ float g_align_scratch[BN * TT * SS];
// bf16-split packed operands (per element 1 u32; pair p -> u32 2p=hi, 2p+1=lo)
__device__ uint32_t g_apk[BN * TT * 768];       // A(out) = concat(c, inputs)
__device__ uint32_t g_wpk[IND * 768];           // Wout
__device__ uint32_t g_wqpk[MD * 512];           // Wq
__device__ uint32_t g_wcpk[MD * 256];           // Wc
__device__ uint32_t g_mpk[BN * SS * 256];       // mems  [row][k=m]  (proj A)
__device__ uint32_t g_mtpk[BN * 256 * 512];     // mems^T [b][m][k=s] (ctx B)
__device__ uint32_t g_ppk[BN * TT * 512];       // P probabilities [row][k=s]

__device__ __forceinline__ float tanhap(float x) {
    float y;
    asm("tanh.approx.f32 %0, %1;" : "=f"(y) : "f"(x));
    return y;
}

__device__ __forceinline__ uint32_t pack_bf2(float x0, float x1) {
    __nv_bfloat162 h = __floats2bfloat162_rn(x0, x1);
    return *reinterpret_cast<uint32_t*>(&h);
}

__device__ __forceinline__ void split2(float x0, float x1,
                                       uint32_t& hi, uint32_t& lo) {
    const float h0 = __bfloat162float(__float2bfloat16_rn(x0));
    const float h1 = __bfloat162float(__float2bfloat16_rn(x1));
    hi = pack_bf2(h0, h1);
    lo = pack_bf2(x0 - h0, x1 - h1);
}

__device__ __forceinline__ void mma_bf(float* cc,
    uint32_t a0, uint32_t a1, uint32_t a2, uint32_t a3,
    uint32_t b0, uint32_t b1)
{
    asm volatile(
        "mma.sync.aligned.m16n8k16.row.col.f32.bf16.bf16.f32 "
        "{%0,%1,%2,%3},{%4,%5,%6,%7},{%8,%9},{%0,%1,%2,%3};"
        : "+f"(cc[0]), "+f"(cc[1]), "+f"(cc[2]), "+f"(cc[3])
        : "r"(a0), "r"(a1), "r"(a2), "r"(a3), "r"(b0), "r"(b1));
}

// ---------------------------------------------------------------------------
// cvt_pre: ALL static packing in one launch (flat-index regions).
// ---------------------------------------------------------------------------
__global__ __launch_bounds__(256) void cvt_pre(
    const float* __restrict__ inputs, const float* __restrict__ mems,
    const float* __restrict__ Wq, const float* __restrict__ Wc,
    const float* __restrict__ Wout)
{
    int idx = blockIdx.x * 256 + threadIdx.x;
    uint32_t hi, lo;
    if (idx < 196608) {                       // R0: Wout
        const int row = idx / 384, p = idx % 384;
        split2(Wout[row * 768 + 2 * p], Wout[row * 768 + 2 * p + 1], hi, lo);
        g_wpk[row * 768 + 2 * p] = hi;
        g_wpk[row * 768 + 2 * p + 1] = lo;
        return;
    }
    idx -= 196608;
    if (idx < 524288) {                       // R1: inputs
        const int row = idx >> 8, q = idx & 255;
        split2(inputs[row * 512 + 2 * q], inputs[row * 512 + 2 * q + 1], hi, lo);
        g_apk[row * 768 + 256 + 2 * q] = hi;
        g_apk[row * 768 + 256 + 2 * q + 1] = lo;
        return;
    }
    idx -= 524288;
    if (idx < 65536) {                        // R2: Wq
        const int row = idx >> 8, p = idx & 255;
        split2(Wq[row * 512 + 2 * p], Wq[row * 512 + 2 * p + 1], hi, lo);
        g_wqpk[row * 512 + 2 * p] = hi;
        g_wqpk[row * 512 + 2 * p + 1] = lo;
        return;
    }
    idx -= 65536;
    if (idx < 32768) {                        // R3: Wc
        const int row = idx >> 7, p = idx & 127;
        split2(Wc[row * 256 + 2 * p], Wc[row * 256 + 2 * p + 1], hi, lo);
        g_wcpk[row * 256 + 2 * p] = hi;
        g_wcpk[row * 256 + 2 * p + 1] = lo;
        return;
    }
    idx -= 32768;
    if (idx < 262144) {                       // R4: mems (proj A layout)
        const int row = idx >> 7, p = idx & 127;
        split2(mems[row * 256 + 2 * p], mems[row * 256 + 2 * p + 1], hi, lo);
        g_mpk[row * 256 + 2 * p] = hi;
        g_mpk[row * 256 + 2 * p + 1] = lo;
        return;
    }
    idx -= 262144;
    {                                         // R5: mems^T (ctx B layout)
        const int b = idx >> 16;
        const int m = (idx >> 8) & 255;
        const int p = idx & 255;
        const float x0 = mems[b * 131072 + (2 * p) * 256 + m];
        const float x1 = mems[b * 131072 + (2 * p + 1) * 256 + m];
        split2(x0, x1, hi, lo);
        g_mtpk[b * 131072 + m * 512 + 2 * p] = hi;
        g_mtpk[b * 131072 + m * 512 + 2 * p + 1] = lo;
    }
}

// ===========================================================================
// Shared 64x64 bf16x3 mma tile machinery (256 thr, 8 warps = 2m x 4n,
// warp tile 32m x 16n, frags c[2 m16][2 n8][4]).  smem pitch 20 u32.
// ===========================================================================
#define MMA_TILE_BODY(ABASE, ASTR, BBASE, BSTR, NIT)                          \
    const int ar0 = tid >> 2, as0 = (tid & 3) * 4;                            \
    uint4 ra0, rb;                                                            \
    auto ldTile = [&](int it) {                                               \
        const int ko = it * 16;                                               \
        ra0 = *(const uint4*)&(ABASE)[(size_t)(bm + ar0) * (ASTR) + ko + as0];\
        rb  = *(const uint4*)&(BBASE)[(size_t)(bn + ar0) * (BSTR) + ko + as0];\
    };                                                                        \
    auto stTile = [&](int bf_) {                                              \
        *(uint4*)&Ash[bf_][ar0 * 20 + as0] = ra0;                             \
        *(uint4*)&Bsh[bf_][ar0 * 20 + as0] = rb;                              \
    };                                                                        \
    ldTile(0);                                                                \
    stTile(0);                                                                \
    __syncthreads();                                                          \
    int buf = 0;                                                              \
    for (int it = 0; it < (NIT); it++) {                                      \
        const bool more = (it + 1 < (NIT));                                   \
        if (more) ldTile(it + 1);                                             \
        const uint32_t* Ab = Ash[buf] + (wm * 32) * 20;                       \
        const uint32_t* Bb = Bsh[buf] + (wn * 16) * 20;                       \
        uint2 af[2][4];                                                       \
        _Pragma("unroll")                                                     \
        for (int m2 = 0; m2 < 2; m2++) {                                      \
            const int r0 = m2 * 16 + g;                                       \
            af[m2][0] = *(const uint2*)&Ab[r0 * 20 + t * 2];                  \
            af[m2][1] = *(const uint2*)&Ab[(r0 + 8) * 20 + t * 2];            \
            af[m2][2] = *(const uint2*)&Ab[r0 * 20 + t * 2 + 8];              \
            af[m2][3] = *(const uint2*)&Ab[(r0 + 8) * 20 + t * 2 + 8];        \
        }                                                                     \
        uint2 bfr[2][2];                                                      \
        _Pragma("unroll")                                                     \
        for (int n2 = 0; n2 < 2; n2++) {                                      \
            const int rn = n2 * 8 + g;                                        \
            bfr[n2][0] = *(const uint2*)&Bb[rn * 20 + t * 2];                 \
            bfr[n2][1] = *(const uint2*)&Bb[rn * 20 + t * 2 + 8];             \
        }                                                                     \
        _Pragma("unroll")                                                     \
        for (int m2 = 0; m2 < 2; m2++)                                        \
            _Pragma("unroll")                                                 \
            for (int n2 = 0; n2 < 2; n2++) {                                  \
                float* cc = c[m2][n2];                                        \
                mma_bf(cc, af[m2][0].x, af[m2][1].x, af[m2][2].x,             \
                       af[m2][3].x, bfr[n2][0].x, bfr[n2][1].x);              \
                mma_bf(cc, af[m2][0].y, af[m2][1].y, af[m2][2].y,             \
                       af[m2][3].y, bfr[n2][0].x, bfr[n2][1].x);              \
                mma_bf(cc, af[m2][0].x, af[m2][1].x, af[m2][2].x,             \
                       af[m2][3].x, bfr[n2][0].y, bfr[n2][1].y);              \
            }                                                                 \
        if (more) stTile(buf ^ 1);                                            \
        __syncthreads();                                                      \
        buf ^= 1;                                                             \
    }

#define MMA_TILE_PREAMBLE                                                     \
    __shared__ uint32_t Ash[2][64 * 20];                                      \
    __shared__ uint32_t Bsh[2][64 * 20];                                      \
    const int tid = threadIdx.x;                                              \
    const int lane = tid & 31;                                                \
    const int warp = tid >> 5;                                                \
    const int wm = warp >> 2, wn = warp & 3;                                  \
    const int g = lane >> 2, t = lane & 3;                                    \
    float c[2][2][4];                                                         \
    _Pragma("unroll")                                                         \
    for (int m2 = 0; m2 < 2; m2++)                                            \
        _Pragma("unroll")                                                     \
        for (int n2 = 0; n2 < 2; n2++)                                        \
            _Pragma("unroll")                                                 \
            for (int q = 0; q < 4; q++) c[m2][n2][q] = 0.f;

// ---------------------------------------------------------------------------
// proj_mma: z=0: g_wq = inputs @ Wq^T (K=512); z=1: g_uht (transposed) + bc.
// Grid (4, 32, 2) = 256 blocks.
// ---------------------------------------------------------------------------
__global__ __launch_bounds__(256) void proj_mma(const float* __restrict__ bc)
{
    MMA_TILE_PREAMBLE
    const int bm = blockIdx.y * 64;
    const int bn = blockIdx.x * 64;
    const int z = blockIdx.z;

    const uint32_t* Abase = z ? g_mpk : (g_apk + 256);
    const int astr = z ? 256 : 768;
    const uint32_t* Bbase = z ? g_wcpk : g_wqpk;
    const int bstr = z ? 256 : 512;
    const int NIT = z ? 16 : 32;

    MMA_TILE_BODY(Abase, astr, Bbase, bstr, NIT)

    if (z == 0) {
#pragma unroll
        for (int m2 = 0; m2 < 2; m2++) {
            const int r0 = bm + wm * 32 + m2 * 16 + g;
#pragma unroll
            for (int n2 = 0; n2 < 2; n2++) {
                const int col = bn + wn * 16 + n2 * 8 + t * 2;
                float* cc = c[m2][n2];
                *(float2*)&g_wq[r0 * MD + col] = make_float2(cc[0], cc[1]);
                *(float2*)&g_wq[(r0 + 8) * MD + col] = make_float2(cc[2], cc[3]);
            }
        }
    } else {
        const int b_ = bm >> 9;
        float* base = g_uht + b_ * (MD * SS);
#pragma unroll
        for (int m2 = 0; m2 < 2; m2++) {
            const int r0 = bm + wm * 32 + m2 * 16 + g;
            const int s0 = r0 & 511, s1 = (r0 + 8) & 511;
#pragma unroll
            for (int n2 = 0; n2 < 2; n2++) {
                const int col = bn + wn * 16 + n2 * 8 + t * 2;
                const float b0v = bc[col], b1v = bc[col + 1];
                float* cc = c[m2][n2];
                base[col * SS + s0] = cc[0] + b0v;
                base[(col + 1) * SS + s0] = cc[1] + b1v;
                base[col * SS + s1] = cc[2] + b0v;
                base[(col + 1) * SS + s1] = cc[3] + b1v;
            }
        }
    }
}

// ---------------------------------------------------------------------------
// align_kernel (at MUFU roofline): 64-s chunks, 16-t tiles.
// ---------------------------------------------------------------------------
__global__ __launch_bounds__(256) void align_kernel(
    const int* __restrict__ mem_masks, const float* __restrict__ v,
    float* __restrict__ pa)
{
    const int b = blockIdx.z;
    const int t0 = blockIdx.y * 16;
    const int c = blockIdx.x;
    const int len = mem_masks[b];
    if (c * 64 >= len) return;

    extern __shared__ float sh[];
    float* uh_sh = sh;                 // [256 d][64 s]
    float* wq_sh = sh + 256 * 64;      // [16][256]
    float* v_sh  = wq_sh + 16 * 256;   // [256]

    const int tid = threadIdx.x;
    const int lane = tid & 31;
    const int warp = tid >> 5;

    {
        const float* src = g_wq + (b * TT + t0) * MD;
        for (int i = tid; i < (16 * 256) / 4; i += 256)
            *(float4*)&wq_sh[i * 4] = *(const float4*)&src[i * 4];
        if (tid < 64)
            *(float4*)&v_sh[tid * 4] = *(const float4*)&v[tid * 4];
        const float* usrc = g_uht + b * (MD * SS) + c * 64;
        for (int i = tid; i < 256 * 16; i += 256) {
            const int d = i >> 4, g = i & 15;
            *(float4*)&uh_sh[d * 64 + g * 4] =
                *(const float4*)&usrc[d * SS + g * 4];
        }
    }
    __syncthreads();

    const int ta = warp * 2;
    const float* wq0 = wq_sh + ta * 256;
    const float* wq1 = wq0 + 256;
    const int sl = lane * 2;
    float2 a0 = make_float2(0.f, 0.f);
    float2 a1 = make_float2(0.f, 0.f);
#pragma unroll 8
    for (int d = 0; d < 256; d++) {
        float2 u = *(float2*)&uh_sh[d * 64 + sl];
        float w0 = wq0[d], w1 = wq1[d], vd = v_sh[d];
        a0.x += vd * tanhap(u.x + w0);
        a0.y += vd * tanhap(u.y + w0);
        a1.x += vd * tanhap(u.x + w1);
        a1.y += vd * tanhap(u.y + w1);
    }
    const int sg = c * 64 + sl;
    *(float2*)&pa[(b * TT + t0 + ta) * SS + sg] = a0;
    *(float2*)&pa[(b * TT + t0 + ta + 1) * SS + sg] = a1;
}

// ---------------------------------------------------------------------------
// softmax_kernel: warp per t-row; fp32 probs -> pa, packed bf16 hi/lo -> g_ppk.
// ---------------------------------------------------------------------------
__global__ __launch_bounds__(256) void softmax_kernel(
    const int* __restrict__ mem_masks, float* __restrict__ pa)
{
    const int lane = threadIdx.x & 31;
    const int warp = threadIdx.x >> 5;
    const int row = blockIdx.x * 8 + warp;
    const int b = row >> 9;
    const int len = mem_masks[b];
    float* prow = pa + row * SS;
    const float NEG = -CUDART_INF_F;

    float vals[16];
    float mx = NEG;
#pragma unroll
    for (int k = 0; k < 16; k++) {
        const int s = lane + k * 32;
        const float val = (s < len) ? prow[s] : NEG;
        vals[k] = val;
        mx = fmaxf(mx, val);
    }
#pragma unroll
    for (int o = 16; o; o >>= 1) mx = fmaxf(mx, __shfl_xor_sync(~0u, mx, o));
    float sum = 0.f;
#pragma unroll
    for (int k = 0; k < 16; k++) {
        const int s = lane + k * 32;
        const float e = (s < len) ? __expf(vals[k] - mx) : 0.f;
        vals[k] = e;
        sum += e;
    }
#pragma unroll
    for (int o = 16; o; o >>= 1) sum += __shfl_xor_sync(~0u, sum, o);
    const float inv = 1.0f / sum;
#pragma unroll
    for (int k = 0; k < 16; k++) {
        const float p = vals[k] * inv;
        prow[lane + k * 32] = p;
        const float pp = __shfl_xor_sync(~0u, p, 1);
        if ((lane & 1) == 0) {
            uint32_t hi, lo;
            split2(p, pp, hi, lo);
            *(uint2*)&g_ppk[row * 512 + lane + k * 32] = make_uint2(hi, lo);
        }
    }
}

// ---------------------------------------------------------------------------
// ctx_mma: split-K=2 over s (len-trimmed). Grid (4, 8, 8) = 256 blocks.
// ---------------------------------------------------------------------------
__global__ __launch_bounds__(256) void ctx_mma(const int* __restrict__ mem_masks)
{
    MMA_TILE_PREAMBLE
    const int b = blockIdx.z >> 1;
    const int kc = blockIdx.z & 1;
    const int bm = blockIdx.y * 64;       // t within b
    const int bn = blockIdx.x * 64;       // m

    const int len = mem_masks[b];
    int rem = len - kc * 256;
    if (rem > 256) rem = 256;
    const int NIT = (rem > 0) ? ((rem + 15) >> 4) : 0;

    const uint32_t* Abase = g_ppk + (b * TT) * 512 + kc * 256;
    const uint32_t* Bbase = g_mtpk + b * (256 * 512) + kc * 256;

    if (NIT > 0) {
        MMA_TILE_BODY(Abase, 512, Bbase, 512, NIT)
    }

    float* dst = g_ctxp[kc];
#pragma unroll
    for (int m2 = 0; m2 < 2; m2++) {
        const int r0 = b * TT + bm + wm * 32 + m2 * 16 + g;
#pragma unroll
        for (int n2 = 0; n2 < 2; n2++) {
            const int col = bn + wn * 16 + n2 * 8 + t * 2;
            float* cc = c[m2][n2];
            *(float2*)&dst[r0 * MD + col] = make_float2(cc[0], cc[1]);
            *(float2*)&dst[(r0 + 8) * MD + col] = make_float2(cc[2], cc[3]);
        }
    }
}

// ---------------------------------------------------------------------------
// cvt_c: fold ctx partials + convert -> packed A k-region [0,256).
// ---------------------------------------------------------------------------
__global__ __launch_bounds__(256) void cvt_c()
{
    const int idx = blockIdx.x * 256 + threadIdx.x;   // 2048*128
    const int row = idx >> 7, q = idx & 127;
    const int e = row * 256 + 2 * q;
    const float x0 = g_ctxp[0][e] + g_ctxp[1][e];
    const float x1 = g_ctxp[0][e + 1] + g_ctxp[1][e + 1];
    uint32_t hi, lo;
    split2(x0, x1, hi, lo);
    const int base = row * 768 + 2 * q;
    g_apk[base] = hi;
    g_apk[base + 1] = lo;
}

// ---------------------------------------------------------------------------
// out_mma: attn_h = A @ Wout^T + bout. Grid (8, 32) = 256 blocks, 48 iters.
// ---------------------------------------------------------------------------
__global__ __launch_bounds__(256) void out_mma(
    const float* __restrict__ bout, float* __restrict__ out)
{
    MMA_TILE_PREAMBLE
    const int bm = blockIdx.y * 64;
    const int bn = blockIdx.x * 64;

    MMA_TILE_BODY(g_apk, 768, g_wpk, 768, 48)

#pragma unroll
    for (int m2 = 0; m2 < 2; m2++) {
        const int r0 = bm + wm * 32 + m2 * 16 + g;
#pragma unroll
        for (int n2 = 0; n2 < 2; n2++) {
            const int col = bn + wn * 16 + n2 * 8 + t * 2;
            const float2 bb = *(const float2*)&bout[col];
            float* cc = c[m2][n2];
            *(float2*)&out[r0 * IND + col] =
                make_float2(cc[0] + bb.x, cc[1] + bb.y);
            *(float2*)&out[(r0 + 8) * IND + col] =
                make_float2(cc[2] + bb.x, cc[3] + bb.y);
        }
    }
}

// ---------------------------------------------------------------------------
extern "C" void kernel_launch(void* const* d_in, const int* in_sizes, int n_in,
                              void* d_out, int out_size)
{
    const float* inputs    = (const float*)d_in[0];
    const float* mems      = (const float*)d_in[1];
    const int*   mem_masks = (const int*)d_in[2];
    const float* Wq        = (const float*)d_in[3];
    const float* Wc        = (const float*)d_in[4];
    const float* bc        = (const float*)d_in[5];
    const float* v         = (const float*)d_in[6];
    const float* Wout      = (const float*)d_in[7];
    const float* bout      = (const float*)d_in[8];

    float* out = (float*)d_out;
    float* pa;
    if (out_size >= BN * TT * IND + BN * TT * SS) {
        pa = out + BN * TT * IND;  // align written in-place in the output
    } else {
        cudaGetSymbolAddress((void**)&pa, g_align_scratch);
    }

    const size_t SMEM_ALIGN = (size_t)(256 * 64 + 16 * 256 + 256) * sizeof(float);
    cudaFuncSetAttribute(align_kernel,
                         cudaFuncAttributeMaxDynamicSharedMemorySize, (int)SMEM_ALIGN);

    cvt_pre<<<5248, 256>>>(inputs, mems, Wq, Wc, Wout);
    proj_mma<<<dim3(4, 32, 2), 256>>>(bc);
    align_kernel<<<dim3(8, 32, 4), 256, SMEM_ALIGN>>>(mem_masks, v, pa);
    softmax_kernel<<<256, 256>>>(mem_masks, pa);
    ctx_mma<<<dim3(4, 8, 8), 256>>>(mem_masks);
    cvt_c<<<1024, 256>>>();
    out_mma<<<dim3(8, 32), 256>>>(bout, out);
}